// round 12
// baseline (speedup 1.0000x reference)
#include <cuda_runtime.h>
#include <cuda_bf16.h>
#include <cstdint>

#define DD    2048
#define NN1   160
#define SROWS 66

typedef unsigned long long ull;

__device__ float g_part[2][8192 * NN1];
__device__ float g_H[8192 * NN1];

__device__ __forceinline__ ull pack2(float v) {
    ull r; asm("mov.b64 %0, {%1, %1};" : "=l"(r) : "f"(v)); return r;
}
__device__ __forceinline__ void fma2(ull &acc, ull a, ull b) {
    asm("fma.rn.f32x2 %0, %1, %2, %0;" : "+l"(acc) : "l"(a), "l"(b));
}
__device__ __forceinline__ void unpack2(ull v, float &lo, float &hi) {
    asm("mov.b64 {%0, %1}, %2;" : "=f"(lo), "=f"(hi) : "l"(v));
}
__device__ __forceinline__ unsigned smem_u32(const void* p) {
    unsigned a; asm("{ .reg .u64 t; cvta.to.shared.u64 t, %1; cvt.u32.u64 %0, t; }" : "=r"(a) : "l"(p));
    return a;
}
__device__ __forceinline__ unsigned packbf2(float lo_val, float hi_val) {
    unsigned p; asm("cvt.rn.bf16x2.f32 %0, %1, %2;" : "=r"(p) : "f"(hi_val), "f"(lo_val));
    return p;   // lo_val in low 16 bits (memory-first element)
}

// ---- mma.sync / ldmatrix (baseline PTX, valid on sm_103 non-'a' target) ----
#define MMA16816(c, a, b0, b1) \
    asm volatile("mma.sync.aligned.m16n8k16.row.col.f32.bf16.bf16.f32 " \
        "{%0,%1,%2,%3}, {%4,%5,%6,%7}, {%8,%9}, {%0,%1,%2,%3};" \
        : "+f"((c)[0]), "+f"((c)[1]), "+f"((c)[2]), "+f"((c)[3]) \
        : "r"((a)[0]), "r"((a)[1]), "r"((a)[2]), "r"((a)[3]), "r"(b0), "r"(b1))
#define LDSM_X4(r, addr) \
    asm volatile("ldmatrix.sync.aligned.m8n8.x4.shared.b16 {%0,%1,%2,%3}, [%4];" \
        : "=r"((r)[0]), "=r"((r)[1]), "=r"((r)[2]), "=r"((r)[3]) : "r"(addr))
#define LDSM_X4T(r, addr) \
    asm volatile("ldmatrix.sync.aligned.m8n8.x4.trans.shared.b16 {%0,%1,%2,%3}, [%4];" \
        : "=r"((r)[0]), "=r"((r)[1]), "=r"((r)[2]), "=r"((r)[3]) : "r"(addr))

// ============================================================================
// Kernel 1: token-shift + xx, fp32 GEMM1 partial (R8 winner, unchanged)
// ============================================================================
__global__ __launch_bounds__(128) void k_gemm1(
    const float* __restrict__ x, const float* __restrict__ state,
    const float* __restrict__ tmx, const float* __restrict__ w1,
    const int* __restrict__ ip, int S)
{
    const int m0 = blockIdx.x * 64, kbeg = blockIdx.y * (DD / 2);
    const int i1 = SROWS * ip[0] + 1;
    __shared__ __align__(16) float As[16][66];
    __shared__ __align__(16) ull   Bsu[16][NN1];
    const int tx = threadIdx.x, n0 = (tx & 31) * 5, mb = (tx >> 5) * 16;
    const int lrow = tx >> 2, lk4 = (tx & 3) * 4;
    ull acc[40];
#pragma unroll
    for (int i = 0; i < 40; ++i) acc[i] = 0ull;
    for (int kt = 0; kt < DD / 2; kt += 16) {
        const int k0 = kbeg + kt;
        const float4 tv = *(const float4*)(tmx + k0 + lk4);
#pragma unroll
        for (int pass = 0; pass < 2; ++pass) {
            const int ml = lrow + pass * 32, m = m0 + ml;
            const float4 xv = *(const float4*)(x + (size_t)m * DD + k0 + lk4);
            float4 pv;
            if ((m % S) == 0)
                pv = *(const float4*)(state + ((size_t)(m / S) * SROWS + i1) * DD + k0 + lk4);
            else
                pv = *(const float4*)(x + (size_t)(m - 1) * DD + k0 + lk4);
            As[lk4 + 0][ml] = fmaf(pv.x - xv.x, tv.x, xv.x);
            As[lk4 + 1][ml] = fmaf(pv.y - xv.y, tv.y, xv.y);
            As[lk4 + 2][ml] = fmaf(pv.z - xv.z, tv.z, xv.z);
            As[lk4 + 3][ml] = fmaf(pv.w - xv.w, tv.w, xv.w);
        }
#pragma unroll
        for (int i = 0; i < 5; ++i) {
            const int idx = tx + i * 128, kk = idx / 40, n4 = (idx - kk * 40) * 4;
            const float4 v = *(const float4*)(w1 + (size_t)(k0 + kk) * NN1 + n4);
            ulonglong2 s0; s0.x = pack2(v.x); s0.y = pack2(v.y);
            ulonglong2 s1; s1.x = pack2(v.z); s1.y = pack2(v.w);
            *(ulonglong2*)&Bsu[kk][n4 + 0] = s0;
            *(ulonglong2*)&Bsu[kk][n4 + 2] = s1;
        }
        __syncthreads();
#pragma unroll
        for (int kk = 0; kk < 16; ++kk) {
            ull bb[5];
#pragma unroll
            for (int j = 0; j < 5; ++j) bb[j] = Bsu[kk][n0 + j];
#pragma unroll
            for (int p = 0; p < 8; ++p) {
                const ull ap = *(const ull*)&As[kk][mb + 2 * p];
#pragma unroll
                for (int j = 0; j < 5; ++j) fma2(acc[p * 5 + j], ap, bb[j]);
            }
        }
        __syncthreads();
    }
    float* dst = g_part[blockIdx.y];
#pragma unroll
    for (int p = 0; p < 8; ++p) {
        const int m = m0 + mb + 2 * p;
#pragma unroll
        for (int j = 0; j < 5; ++j) {
            float lo, hi; unpack2(acc[p * 5 + j], lo, hi);
            dst[(size_t)m * NN1 + n0 + j]       = lo;
            dst[(size_t)(m + 1) * NN1 + n0 + j] = hi;
        }
    }
}

__device__ __forceinline__ float ftanh(float v) {
    v = fminf(fmaxf(v, -10.f), 10.f);
    const float e = __expf(2.f * v);
    return __fdividef(e - 1.f, e + 1.f);
}
__global__ void k_act(int total4)
{
    const int idx = blockIdx.x * blockDim.x + threadIdx.x;
    if (idx >= total4) return;
    const float4 a = ((const float4*)g_part[0])[idx];
    const float4 b = ((const float4*)g_part[1])[idx];
    float4 o;
    o.x = ftanh(a.x + b.x); o.y = ftanh(a.y + b.y);
    o.z = ftanh(a.z + b.z); o.w = ftanh(a.w + b.w);
    ((float4*)g_H)[idx] = o;
}

// ============================================================================
// Kernel 2: mma.sync bf16x3 GEMM2 + fused combine.
//   CTA: 64 tokens x 256 d, 8 warps (warp = 16 tok x 128 d).
//   Per f: stage A=[Hhi|Hlo] [64 x 64] bf16 (row pad 72), B hi/lo [32 x 264].
//   ldmatrix.x4 (A) / ldmatrix.x4.trans (B); 6 mma per n8 tile (3 terms x k32).
//   Epilogue: C frags -> padded smem (union with stage bufs) -> coalesced
//   fused out = x + sx*(maa+acc) float4 stores.
// ============================================================================
#define AS_OFF   0
#define BHI_OFF  9216
#define BLO_OFF  26112
#define ASTRIDE  72
#define BSTRIDE  264
#define ESTRIDE  272
#define SMEM_SZ  69632   // 64 * 272 * 4 (epilogue buffer dominates)

__global__ __launch_bounds__(256, 2) void k_gemm2(
    const float* __restrict__ x, const float* __restrict__ state,
    const float* __restrict__ w2,
    const float* __restrict__ mk, const float* __restrict__ mw,
    const float* __restrict__ mv, const float* __restrict__ mr,
    const float* __restrict__ mg,
    const int* __restrict__ ip, float* __restrict__ out, int S)
{
    extern __shared__ __align__(16) char smem[];
    const unsigned sb = smem_u32(smem);
    const int m0 = blockIdx.x * 64, dbase = blockIdx.y * 256;
    const int tx = threadIdx.x, wid = tx >> 5, lane = tx & 31;
    const int wm = wid & 3, wn = wid >> 2;              // warp tile: tokens, d-half
    const int i1 = SROWS * ip[0] + 1;

    // ldmatrix lane addressing (shared by A and B-trans):
    const int lrow = (lane & 7) + ((lane & 8) ? 8 : 0); // tile row within 16
    const int lcol = (lane & 16) ? 8 : 0;               // second tile-column

#pragma unroll 1
    for (int f = 0; f < 5; ++f) {
        // ---- stage A: H[m0+t][f*32+k] -> hi at col k, lo at col 32+k ----
#pragma unroll
        for (int i = 0; i < 2; ++i) {
            const int idx = tx + i * 256;               // 512 float4
            const int t = idx >> 3, k4 = (idx & 7) * 4;
            const float4 v = *(const float4*)(g_H + (size_t)(m0 + t) * NN1 + f * 32 + k4);
            const float e0 = __bfloat162float(__float2bfloat16(v.x));
            const float e1 = __bfloat162float(__float2bfloat16(v.y));
            const float e2 = __bfloat162float(__float2bfloat16(v.z));
            const float e3 = __bfloat162float(__float2bfloat16(v.w));
            uint2 hi; hi.x = packbf2(v.x, v.y); hi.y = packbf2(v.z, v.w);
            uint2 lo; lo.x = packbf2(v.x - e0, v.y - e1); lo.y = packbf2(v.z - e2, v.w - e3);
            *(uint2*)(smem + AS_OFF + (t * ASTRIDE + k4) * 2)      = hi;
            *(uint2*)(smem + AS_OFF + (t * ASTRIDE + 32 + k4) * 2) = lo;
        }
        // ---- stage B: w2[f,k,dtile] -> Bhi/Blo [k][n], row pad 264 ----
        const float* w2f = w2 + (size_t)(f * 32) * DD + dbase;
#pragma unroll
        for (int i = 0; i < 8; ++i) {
            const int idx = tx + i * 256;               // 2048 float4
            const int k = idx >> 6, d4 = (idx & 63) * 4;
            const float4 v = *(const float4*)(w2f + (size_t)k * DD + d4);
            const float e0 = __bfloat162float(__float2bfloat16(v.x));
            const float e1 = __bfloat162float(__float2bfloat16(v.y));
            const float e2 = __bfloat162float(__float2bfloat16(v.z));
            const float e3 = __bfloat162float(__float2bfloat16(v.w));
            uint2 hi; hi.x = packbf2(v.x, v.y); hi.y = packbf2(v.z, v.w);
            uint2 lo; lo.x = packbf2(v.x - e0, v.y - e1); lo.y = packbf2(v.z - e2, v.w - e3);
            *(uint2*)(smem + BHI_OFF + (k * BSTRIDE + d4) * 2) = hi;
            *(uint2*)(smem + BLO_OFF + (k * BSTRIDE + d4) * 2) = lo;
        }
        __syncthreads();

        // ---- A fragments (once per f per warp) ----
        unsigned ahi[2][4], alo[2][4];
        {
            const unsigned abase = sb + AS_OFF + ((wm * 16 + lrow) * ASTRIDE) * 2;
#pragma unroll
            for (int s = 0; s < 2; ++s) {
                LDSM_X4(ahi[s], abase + (s * 16 + lcol) * 2);
                LDSM_X4(alo[s], abase + (32 + s * 16 + lcol) * 2);
            }
        }

        float acc[8][2][4];
#pragma unroll
        for (int c = 0; c < 8; ++c)
#pragma unroll
            for (int j = 0; j < 2; ++j)
#pragma unroll
                for (int q = 0; q < 4; ++q) acc[c][j][q] = 0.f;

        // ---- mma over 8 n16 chunks ----
#pragma unroll 1
        for (int c = 0; c < 8; ++c) {
            const int ncol = wn * 128 + c * 16 + lcol;
            unsigned bh[2][4], bl[2][4];
#pragma unroll
            for (int s = 0; s < 2; ++s) {
                LDSM_X4T(bh[s], sb + BHI_OFF + ((s * 16 + lrow) * BSTRIDE + ncol) * 2);
                LDSM_X4T(bl[s], sb + BLO_OFF + ((s * 16 + lrow) * BSTRIDE + ncol) * 2);
            }
#pragma unroll
            for (int j = 0; j < 2; ++j)
#pragma unroll
                for (int s = 0; s < 2; ++s) {
                    MMA16816(acc[c][j], ahi[s], bh[s][2 * j], bh[s][2 * j + 1]);
                    MMA16816(acc[c][j], alo[s], bh[s][2 * j], bh[s][2 * j + 1]);
                    MMA16816(acc[c][j], ahi[s], bl[s][2 * j], bl[s][2 * j + 1]);
                }
        }
        __syncthreads();   // all warps done reading A/B before buffer overwrite

        // ---- C frags -> padded smem buffer [64][272] ----
        {
            float* buf = (float*)smem;
            const int crow = wm * 16 + (lane >> 2);
            const int ccol = wn * 128 + (lane & 3) * 2;
#pragma unroll
            for (int c = 0; c < 8; ++c)
#pragma unroll
                for (int j = 0; j < 2; ++j) {
                    const int n = ccol + c * 16 + j * 8;
                    *(float2*)(buf + crow * ESTRIDE + n)       = make_float2(acc[c][j][0], acc[c][j][1]);
                    *(float2*)(buf + (crow + 8) * ESTRIDE + n) = make_float2(acc[c][j][2], acc[c][j][3]);
                }
        }
        __syncthreads();

        // ---- fused epilogue: out = x + (xprev-x)*(maa+acc), float4 ----
        const float* maa = (f == 0 ? mk : f == 1 ? mw : f == 2 ? mv : f == 3 ? mr : mg);
        {
            const float* buf = (const float*)smem;
            const int t = tx >> 2, q = tx & 3, m = m0 + t;
            const float* xr = x + (size_t)m * DD + dbase;
            const float* pr = ((m % S) == 0)
                ? state + ((size_t)(m / S) * SROWS + i1) * DD + dbase
                : xr - DD;
            float* orow = out + ((size_t)m * 5 + f) * DD + dbase;
            const float* br = buf + t * ESTRIDE;
#pragma unroll
            for (int v = 0; v < 16; ++v) {
                const int j4 = (q + 4 * v) * 4;
                const float4 a  = *(const float4*)(br + j4);
                const float4 xv = *(const float4*)(xr + j4);
                const float4 pv = *(const float4*)(pr + j4);
                const float4 mm = *(const float4*)(maa + dbase + j4);
                float4 o;
                o.x = fmaf(pv.x - xv.x, mm.x + a.x, xv.x);
                o.y = fmaf(pv.y - xv.y, mm.y + a.y, xv.y);
                o.z = fmaf(pv.z - xv.z, mm.z + a.z, xv.z);
                o.w = fmaf(pv.w - xv.w, mm.w + a.w, xv.w);
                *(float4*)(orow + j4) = o;
            }
        }
        __syncthreads();
    }
}

__global__ void k_state(const float* __restrict__ x, const float* __restrict__ state,
                        const int* __restrict__ ip, float* __restrict__ out2,
                        int S, int total4)
{
    const int idx = blockIdx.x * blockDim.x + threadIdx.x;
    if (idx >= total4) return;
    const int i1 = SROWS * ip[0] + 1;
    const int D4 = DD / 4;
    const int d4 = idx & (D4 - 1), r = (idx / D4) % SROWS, b = idx / (D4 * SROWS);
    float4 v;
    if (r == i1) v = ((const float4*)x)[((size_t)b * S + (S - 1)) * D4 + d4];
    else         v = ((const float4*)state)[idx];
    ((float4*)out2)[idx] = v;
}

extern "C" void kernel_launch(void* const* d_in, const int* in_sizes, int n_in,
                              void* d_out, int out_size)
{
    const float* x     = (const float*)d_in[0];
    const float* state = (const float*)d_in[1];
    const float* tmx   = (const float*)d_in[2];
    const float* w1    = (const float*)d_in[3];
    const float* w2    = (const float*)d_in[4];
    const float* mk    = (const float*)d_in[5];
    const float* mw    = (const float*)d_in[6];
    const float* mv    = (const float*)d_in[7];
    const float* mr    = (const float*)d_in[8];
    const float* mg    = (const float*)d_in[9];
    const int*   ip    = (const int*)  d_in[10];
    float* out = (float*)d_out;

    const int B = in_sizes[1] / (SROWS * DD);
    const int S = in_sizes[0] / (B * DD);
    const int M = B * S;

    static bool attr_set = false;
    if (!attr_set) {
        cudaFuncSetAttribute(k_gemm2, cudaFuncAttributeMaxDynamicSharedMemorySize, SMEM_SZ);
        attr_set = true;
    }

    k_gemm1<<<dim3(M / 64, 2), 128>>>(x, state, tmx, w1, ip, S);
    const int act4 = (M * NN1) / 4;
    k_act<<<(act4 + 255) / 256, 256>>>(act4);
    k_gemm2<<<dim3(M / 64, DD / 256), 256, SMEM_SZ>>>(x, state, w2, mk, mw, mv, mr, mg, ip, out, S);

    const long long kw = (long long)M * 5 * DD;
    const int st_total = B * SROWS * DD;
    if ((long long)out_size >= kw + (long long)st_total) {
        k_state<<<(st_total / 4 + 255) / 256, 256>>>(x, state, ip, out + kw, S, st_total / 4);
    }
}

// round 13
// speedup vs baseline: 1.1052x; 1.1052x over previous
#include <cuda_runtime.h>
#include <cuda_bf16.h>
#include <cstdint>

#define DD    2048
#define NN1   160
#define SROWS 66

typedef unsigned long long ull;
typedef unsigned short u16;

__device__ float g_part[2][8192 * NN1];
__device__ u16 g_Hhi[8192 * NN1];      // tanh(H) bf16 hi plane
__device__ u16 g_Hlo[8192 * NN1];      // residual lo plane
__device__ u16 g_Whi[NN1 * DD];        // w2 bf16 hi plane
__device__ u16 g_Wlo[NN1 * DD];        // w2 lo plane

__device__ __forceinline__ ull pack2(float v) {
    ull r; asm("mov.b64 %0, {%1, %1};" : "=l"(r) : "f"(v)); return r;
}
__device__ __forceinline__ void fma2(ull &acc, ull a, ull b) {
    asm("fma.rn.f32x2 %0, %1, %2, %0;" : "+l"(acc) : "l"(a), "l"(b));
}
__device__ __forceinline__ void unpack2(ull v, float &lo, float &hi) {
    asm("mov.b64 {%0, %1}, %2;" : "=f"(lo), "=f"(hi) : "l"(v));
}
__device__ __forceinline__ unsigned smem_u32(const void* p) {
    unsigned a; asm("{ .reg .u64 t; cvta.to.shared.u64 t, %1; cvt.u32.u64 %0, t; }" : "=r"(a) : "l"(p));
    return a;
}
__device__ __forceinline__ unsigned packbf2(float lo_val, float hi_val) {
    unsigned p; asm("cvt.rn.bf16x2.f32 %0, %1, %2;" : "=r"(p) : "f"(hi_val), "f"(lo_val));
    return p;   // lo_val in low 16 bits
}

#define MMA16816(c, a, b0, b1) \
    asm volatile("mma.sync.aligned.m16n8k16.row.col.f32.bf16.bf16.f32 " \
        "{%0,%1,%2,%3}, {%4,%5,%6,%7}, {%8,%9}, {%0,%1,%2,%3};" \
        : "+f"((c)[0]), "+f"((c)[1]), "+f"((c)[2]), "+f"((c)[3]) \
        : "r"((a)[0]), "r"((a)[1]), "r"((a)[2]), "r"((a)[3]), "r"(b0), "r"(b1))
#define LDSM_X4(r, addr) \
    asm volatile("ldmatrix.sync.aligned.m8n8.x4.shared.b16 {%0,%1,%2,%3}, [%4];" \
        : "=r"((r)[0]), "=r"((r)[1]), "=r"((r)[2]), "=r"((r)[3]) : "r"(addr))
#define LDSM_X4T(r, addr) \
    asm volatile("ldmatrix.sync.aligned.m8n8.x4.trans.shared.b16 {%0,%1,%2,%3}, [%4];" \
        : "=r"((r)[0]), "=r"((r)[1]), "=r"((r)[2]), "=r"((r)[3]) : "r"(addr))

// ============================================================================
// Kernel 1: token-shift + xx, fp32 GEMM1 partial (R8 winner, unchanged)
// ============================================================================
__global__ __launch_bounds__(128) void k_gemm1(
    const float* __restrict__ x, const float* __restrict__ state,
    const float* __restrict__ tmx, const float* __restrict__ w1,
    const int* __restrict__ ip, int S)
{
    const int m0 = blockIdx.x * 64, kbeg = blockIdx.y * (DD / 2);
    const int i1 = SROWS * ip[0] + 1;
    __shared__ __align__(16) float As[16][66];
    __shared__ __align__(16) ull   Bsu[16][NN1];
    const int tx = threadIdx.x, n0 = (tx & 31) * 5, mb = (tx >> 5) * 16;
    const int lrow = tx >> 2, lk4 = (tx & 3) * 4;
    ull acc[40];
#pragma unroll
    for (int i = 0; i < 40; ++i) acc[i] = 0ull;
    for (int kt = 0; kt < DD / 2; kt += 16) {
        const int k0 = kbeg + kt;
        const float4 tv = *(const float4*)(tmx + k0 + lk4);
#pragma unroll
        for (int pass = 0; pass < 2; ++pass) {
            const int ml = lrow + pass * 32, m = m0 + ml;
            const float4 xv = *(const float4*)(x + (size_t)m * DD + k0 + lk4);
            float4 pv;
            if ((m % S) == 0)
                pv = *(const float4*)(state + ((size_t)(m / S) * SROWS + i1) * DD + k0 + lk4);
            else
                pv = *(const float4*)(x + (size_t)(m - 1) * DD + k0 + lk4);
            As[lk4 + 0][ml] = fmaf(pv.x - xv.x, tv.x, xv.x);
            As[lk4 + 1][ml] = fmaf(pv.y - xv.y, tv.y, xv.y);
            As[lk4 + 2][ml] = fmaf(pv.z - xv.z, tv.z, xv.z);
            As[lk4 + 3][ml] = fmaf(pv.w - xv.w, tv.w, xv.w);
        }
#pragma unroll
        for (int i = 0; i < 5; ++i) {
            const int idx = tx + i * 128, kk = idx / 40, n4 = (idx - kk * 40) * 4;
            const float4 v = *(const float4*)(w1 + (size_t)(k0 + kk) * NN1 + n4);
            ulonglong2 s0; s0.x = pack2(v.x); s0.y = pack2(v.y);
            ulonglong2 s1; s1.x = pack2(v.z); s1.y = pack2(v.w);
            *(ulonglong2*)&Bsu[kk][n4 + 0] = s0;
            *(ulonglong2*)&Bsu[kk][n4 + 2] = s1;
        }
        __syncthreads();
#pragma unroll
        for (int kk = 0; kk < 16; ++kk) {
            ull bb[5];
#pragma unroll
            for (int j = 0; j < 5; ++j) bb[j] = Bsu[kk][n0 + j];
#pragma unroll
            for (int p = 0; p < 8; ++p) {
                const ull ap = *(const ull*)&As[kk][mb + 2 * p];
#pragma unroll
                for (int j = 0; j < 5; ++j) fma2(acc[p * 5 + j], ap, bb[j]);
            }
        }
        __syncthreads();
    }
    float* dst = g_part[blockIdx.y];
#pragma unroll
    for (int p = 0; p < 8; ++p) {
        const int m = m0 + mb + 2 * p;
#pragma unroll
        for (int j = 0; j < 5; ++j) {
            float lo, hi; unpack2(acc[p * 5 + j], lo, hi);
            dst[(size_t)m * NN1 + n0 + j]       = lo;
            dst[(size_t)(m + 1) * NN1 + n0 + j] = hi;
        }
    }
}

// ============================================================================
// Kernel 1b: partials + tanh -> H bf16 hi/lo planes
// ============================================================================
__device__ __forceinline__ float ftanh(float v) {
    v = fminf(fmaxf(v, -10.f), 10.f);
    const float e = __expf(2.f * v);
    return __fdividef(e - 1.f, e + 1.f);
}
__global__ void k_act(int total4)
{
    const int idx = blockIdx.x * blockDim.x + threadIdx.x;
    if (idx >= total4) return;
    const float4 a = ((const float4*)g_part[0])[idx];
    const float4 b = ((const float4*)g_part[1])[idx];
    const float t0 = ftanh(a.x + b.x), t1 = ftanh(a.y + b.y);
    const float t2 = ftanh(a.z + b.z), t3 = ftanh(a.w + b.w);
    const unsigned h0 = packbf2(t0, t1), h1 = packbf2(t2, t3);
    const float e0 = __uint_as_float(h0 << 16), e1 = __uint_as_float(h0 & 0xFFFF0000u);
    const float e2 = __uint_as_float(h1 << 16), e3 = __uint_as_float(h1 & 0xFFFF0000u);
    *(uint2*)&g_Hhi[idx * 4] = make_uint2(h0, h1);
    *(uint2*)&g_Hlo[idx * 4] = make_uint2(packbf2(t0 - e0, t1 - e1), packbf2(t2 - e2, t3 - e3));
}

// ============================================================================
// Kernel 1c: w2 -> bf16 hi/lo planes (once per launch, ~4us)
// ============================================================================
__global__ void k_w2cvt(const float* __restrict__ w2, int total4)
{
    const int idx = blockIdx.x * blockDim.x + threadIdx.x;
    if (idx >= total4) return;
    const float4 v = ((const float4*)w2)[idx];
    const unsigned h0 = packbf2(v.x, v.y), h1 = packbf2(v.z, v.w);
    const float e0 = __uint_as_float(h0 << 16), e1 = __uint_as_float(h0 & 0xFFFF0000u);
    const float e2 = __uint_as_float(h1 << 16), e3 = __uint_as_float(h1 & 0xFFFF0000u);
    *(uint2*)&g_Whi[idx * 4] = make_uint2(h0, h1);
    *(uint2*)&g_Wlo[idx * 4] = make_uint2(packbf2(v.x - e0, v.y - e1), packbf2(v.z - e2, v.w - e3));
}

// ============================================================================
// Kernel 2: mma.sync bf16x3 GEMM2 + fused combine (v2: pre-converted planes,
//   half-split accumulators -> no spill, epilogue buffer beside A/B tiles).
//   CTA: 64 tok x 256 d; warp = 16 tok x 64 d per half; 2 halves of 128 d.
// ============================================================================
#define AS_OFF   0
#define BHI_OFF  9216
#define BLO_OFF  26112
#define EPI_OFF  43008
#define ASTRIDE  72
#define BSTRIDE  264
#define ESTRIDE  136
#define SMEM_SZ  77824

__global__ __launch_bounds__(256, 2) void k_gemm2(
    const float* __restrict__ x, const float* __restrict__ state,
    const float* __restrict__ mk, const float* __restrict__ mw,
    const float* __restrict__ mv, const float* __restrict__ mr,
    const float* __restrict__ mg,
    const int* __restrict__ ip, float* __restrict__ out, int S)
{
    extern __shared__ __align__(16) char smem[];
    const unsigned sb = smem_u32(smem);
    float* epi = (float*)(smem + EPI_OFF);
    const int m0 = blockIdx.x * 64, dbase = blockIdx.y * 256;
    const int tx = threadIdx.x, wid = tx >> 5, lane = tx & 31;
    const int wm = wid & 3, wn = wid >> 2;
    const int i1 = SROWS * ip[0] + 1;

    const int lrow = (lane & 7) + ((lane & 8) ? 8 : 0);
    const int lcol = (lane & 16) ? 8 : 0;

#pragma unroll 1
    for (int f = 0; f < 5; ++f) {
        // ---- stage A: H planes, [t][hi k 0..31 | lo k 32..63], pad 72 ----
#pragma unroll
        for (int i = 0; i < 4; ++i) {
            const int idx = tx + i * 256;            // 1024 uint2
            const int plane = idx >> 9, r = idx & 511, t = r >> 3, u = r & 7;
            const u16* src = (plane ? g_Hlo : g_Hhi) + (size_t)(m0 + t) * NN1 + f * 32 + u * 4;
            *(uint2*)(smem + AS_OFF + (t * ASTRIDE + plane * 32 + u * 4) * 2) = *(const uint2*)src;
        }
        // ---- stage B: w2 planes, [k][d 0..255], pad 264 ----
#pragma unroll
        for (int i = 0; i < 8; ++i) {
            const int idx = tx + i * 256;            // 2048 uint4
            const int plane = idx >> 10, r = idx & 1023, k = r >> 5, u = r & 31;
            const u16* src = (plane ? g_Wlo : g_Whi) + (size_t)(f * 32 + k) * DD + dbase + u * 8;
            char* dst = smem + (plane ? BLO_OFF : BHI_OFF) + (k * BSTRIDE + u * 8) * 2;
            *(uint4*)dst = *(const uint4*)src;
        }
        __syncthreads();   // S0

        unsigned ahi[2][4], alo[2][4];
        {
            const unsigned abase = sb + AS_OFF + ((wm * 16 + lrow) * ASTRIDE) * 2;
#pragma unroll
            for (int s = 0; s < 2; ++s) {
                LDSM_X4(ahi[s], abase + (s * 16 + lcol) * 2);
                LDSM_X4(alo[s], abase + (32 + s * 16 + lcol) * 2);
            }
        }

        const float* maa = (f == 0 ? mk : f == 1 ? mw : f == 2 ? mv : f == 3 ? mr : mg);

#pragma unroll 1
        for (int h = 0; h < 2; ++h) {
            float acc[4][2][4];
#pragma unroll
            for (int c = 0; c < 4; ++c)
#pragma unroll
                for (int j = 0; j < 2; ++j)
#pragma unroll
                    for (int q = 0; q < 4; ++q) acc[c][j][q] = 0.f;

#pragma unroll 1
            for (int c = 0; c < 4; ++c) {
                const int ncol = h * 128 + wn * 64 + c * 16 + lcol;
                unsigned bh[2][4], bl[2][4];
#pragma unroll
                for (int s = 0; s < 2; ++s) {
                    LDSM_X4T(bh[s], sb + BHI_OFF + ((s * 16 + lrow) * BSTRIDE + ncol) * 2);
                    LDSM_X4T(bl[s], sb + BLO_OFF + ((s * 16 + lrow) * BSTRIDE + ncol) * 2);
                }
#pragma unroll
                for (int j = 0; j < 2; ++j)
#pragma unroll
                    for (int s = 0; s < 2; ++s) {
                        MMA16816(acc[c][j], ahi[s], bh[s][2 * j], bh[s][2 * j + 1]);
                        MMA16816(acc[c][j], alo[s], bh[s][2 * j], bh[s][2 * j + 1]);
                        MMA16816(acc[c][j], ahi[s], bl[s][2 * j], bl[s][2 * j + 1]);
                    }
            }
            __syncthreads();   // S1: previous epilogue readers done

            {   // C frags -> epi buffer [64][136] (half columns 0..127)
                const int crow = wm * 16 + (lane >> 2);
                const int ccol = wn * 64 + (lane & 3) * 2;
#pragma unroll
                for (int c = 0; c < 4; ++c)
#pragma unroll
                    for (int j = 0; j < 2; ++j) {
                        const int n = ccol + c * 16 + j * 8;
                        *(float2*)(epi + crow * ESTRIDE + n)       = make_float2(acc[c][j][0], acc[c][j][1]);
                        *(float2*)(epi + (crow + 8) * ESTRIDE + n) = make_float2(acc[c][j][2], acc[c][j][3]);
                    }
            }
            __syncthreads();   // S2

            {   // fused epilogue for this 128-col half, coalesced float4
                const int t = tx >> 2, q = tx & 3, m = m0 + t;
                const int dch = dbase + h * 128;
                const float* xr = x + (size_t)m * DD + dch;
                const float* pr = ((m % S) == 0)
                    ? state + ((size_t)(m / S) * SROWS + i1) * DD + dch
                    : xr - DD;
                float* orow = out + ((size_t)m * 5 + f) * DD + dch;
                const float* br = epi + t * ESTRIDE;
#pragma unroll
                for (int v = 0; v < 8; ++v) {
                    const int j4 = (q + 4 * v) * 4;
                    const float4 a  = *(const float4*)(br + j4);
                    const float4 xv = *(const float4*)(xr + j4);
                    const float4 pv = *(const float4*)(pr + j4);
                    const float4 mm = *(const float4*)(maa + dch + j4);
                    float4 o;
                    o.x = fmaf(pv.x - xv.x, mm.x + a.x, xv.x);
                    o.y = fmaf(pv.y - xv.y, mm.y + a.y, xv.y);
                    o.z = fmaf(pv.z - xv.z, mm.z + a.z, xv.z);
                    o.w = fmaf(pv.w - xv.w, mm.w + a.w, xv.w);
                    *(float4*)(orow + j4) = o;
                }
            }
        }
    }
}

__global__ void k_state(const float* __restrict__ x, const float* __restrict__ state,
                        const int* __restrict__ ip, float* __restrict__ out2,
                        int S, int total4)
{
    const int idx = blockIdx.x * blockDim.x + threadIdx.x;
    if (idx >= total4) return;
    const int i1 = SROWS * ip[0] + 1;
    const int D4 = DD / 4;
    const int d4 = idx & (D4 - 1), r = (idx / D4) % SROWS, b = idx / (D4 * SROWS);
    float4 v;
    if (r == i1) v = ((const float4*)x)[((size_t)b * S + (S - 1)) * D4 + d4];
    else         v = ((const float4*)state)[idx];
    ((float4*)out2)[idx] = v;
}

extern "C" void kernel_launch(void* const* d_in, const int* in_sizes, int n_in,
                              void* d_out, int out_size)
{
    const float* x     = (const float*)d_in[0];
    const float* state = (const float*)d_in[1];
    const float* tmx   = (const float*)d_in[2];
    const float* w1    = (const float*)d_in[3];
    const float* w2    = (const float*)d_in[4];
    const float* mk    = (const float*)d_in[5];
    const float* mw    = (const float*)d_in[6];
    const float* mv    = (const float*)d_in[7];
    const float* mr    = (const float*)d_in[8];
    const float* mg    = (const float*)d_in[9];
    const int*   ip    = (const int*)  d_in[10];
    float* out = (float*)d_out;

    const int B = in_sizes[1] / (SROWS * DD);
    const int S = in_sizes[0] / (B * DD);
    const int M = B * S;

    cudaFuncSetAttribute(k_gemm2, cudaFuncAttributeMaxDynamicSharedMemorySize, SMEM_SZ);

    k_gemm1<<<dim3(M / 64, 2), 128>>>(x, state, tmx, w1, ip, S);
    const int act4 = (M * NN1) / 4;
    k_act<<<(act4 + 255) / 256, 256>>>(act4);
    const int w4 = (NN1 * DD) / 4;
    k_w2cvt<<<(w4 + 255) / 256, 256>>>(w2, w4);
    k_gemm2<<<dim3(M / 64, DD / 256), 256, SMEM_SZ>>>(x, state, mk, mw, mv, mr, mg, ip, out, S);

    const long long kw = (long long)M * 5 * DD;
    const int st_total = B * SROWS * DD;
    if ((long long)out_size >= kw + (long long)st_total) {
        k_state<<<(st_total / 4 + 255) / 256, 256>>>(x, state, ip, out + kw, S, st_total / 4);
    }
}

// round 15
// speedup vs baseline: 1.2874x; 1.1649x over previous
#include <cuda_runtime.h>
#include <cuda_bf16.h>
#include <cstdint>

#define DD    2048
#define NN1   160
#define SROWS 66

typedef unsigned short u16;

// Static device scratch (no allocations allowed).
__device__ u16 g_Hhi[8192 * NN1];      // tanh(xx@w1) bf16 hi plane
__device__ u16 g_Hlo[8192 * NN1];      // residual lo plane
__device__ u16 g_W1hi[2048 * NN1];     // w1 planes
__device__ u16 g_W1lo[2048 * NN1];
__device__ u16 g_Whi[NN1 * DD];        // w2 planes
__device__ u16 g_Wlo[NN1 * DD];

__device__ __forceinline__ unsigned smem_u32(const void* p) {
    unsigned a; asm("{ .reg .u64 t; cvta.to.shared.u64 t, %1; cvt.u32.u64 %0, t; }" : "=r"(a) : "l"(p));
    return a;
}
__device__ __forceinline__ unsigned packbf2(float lo_val, float hi_val) {
    unsigned p; asm("cvt.rn.bf16x2.f32 %0, %1, %2;" : "=r"(p) : "f"(hi_val), "f"(lo_val));
    return p;   // lo_val in low 16 bits (element at lower address)
}
__device__ __forceinline__ float ftanh(float v) {
    v = fminf(fmaxf(v, -10.f), 10.f);
    const float e = __expf(2.f * v);
    return __fdividef(e - 1.f, e + 1.f);
}

#define MMA16816(c, a, b0, b1) \
    asm volatile("mma.sync.aligned.m16n8k16.row.col.f32.bf16.bf16.f32 " \
        "{%0,%1,%2,%3}, {%4,%5,%6,%7}, {%8,%9}, {%0,%1,%2,%3};" \
        : "+f"((c)[0]), "+f"((c)[1]), "+f"((c)[2]), "+f"((c)[3]) \
        : "r"((a)[0]), "r"((a)[1]), "r"((a)[2]), "r"((a)[3]), "r"(b0), "r"(b1))
#define LDSM_X4(r, addr) \
    asm volatile("ldmatrix.sync.aligned.m8n8.x4.shared.b16 {%0,%1,%2,%3}, [%4];" \
        : "=r"((r)[0]), "=r"((r)[1]), "=r"((r)[2]), "=r"((r)[3]) : "r"(addr))
#define LDSM_X4T(r, addr) \
    asm volatile("ldmatrix.sync.aligned.m8n8.x4.trans.shared.b16 {%0,%1,%2,%3}, [%4];" \
        : "=r"((r)[0]), "=r"((r)[1]), "=r"((r)[2]), "=r"((r)[3]) : "r"(addr))

// ============================================================================
// Weight plane conversions (once per launch; w1 and w2 both 327680 floats)
// ============================================================================
__global__ void k_w1cvt(const float* __restrict__ w, int total4)
{
    const int idx = blockIdx.x * blockDim.x + threadIdx.x;
    if (idx >= total4) return;
    const float4 v = ((const float4*)w)[idx];
    const unsigned h0 = packbf2(v.x, v.y), h1 = packbf2(v.z, v.w);
    const float e0 = __uint_as_float(h0 << 16), e1 = __uint_as_float(h0 & 0xFFFF0000u);
    const float e2 = __uint_as_float(h1 << 16), e3 = __uint_as_float(h1 & 0xFFFF0000u);
    *(uint2*)&g_W1hi[idx * 4] = make_uint2(h0, h1);
    *(uint2*)&g_W1lo[idx * 4] = make_uint2(packbf2(v.x - e0, v.y - e1), packbf2(v.z - e2, v.w - e3));
}
__global__ void k_w2cvt(const float* __restrict__ w, int total4)
{
    const int idx = blockIdx.x * blockDim.x + threadIdx.x;
    if (idx >= total4) return;
    const float4 v = ((const float4*)w)[idx];
    const unsigned h0 = packbf2(v.x, v.y), h1 = packbf2(v.z, v.w);
    const float e0 = __uint_as_float(h0 << 16), e1 = __uint_as_float(h0 & 0xFFFF0000u);
    const float e2 = __uint_as_float(h1 << 16), e3 = __uint_as_float(h1 & 0xFFFF0000u);
    *(uint2*)&g_Whi[idx * 4] = make_uint2(h0, h1);
    *(uint2*)&g_Wlo[idx * 4] = make_uint2(packbf2(v.x - e0, v.y - e1), packbf2(v.z - e2, v.w - e3));
}

// ============================================================================
// Kernel 1: mma.sync bf16x3 GEMM1, fused token-shift (A staging) and
//   tanh + H-plane emission (epilogue). CTA: 32 tok x 160 n, 10 warps.
//   Warp: 16 tok x 32 n. K loop: 64 tiles of 32.
// ============================================================================
#define G1_AS    0
#define G1_BHI   4608                  // 32*72*2
#define G1_BLO   15360                 // 4608 + 32*168*2
#define G1_ASTR  72
#define G1_BSTR  168
#define G1_SMEM  26112

__global__ __launch_bounds__(320) void k_gemm1(
    const float* __restrict__ x, const float* __restrict__ state,
    const float* __restrict__ tmx, const int* __restrict__ ip, int S)
{
    __shared__ __align__(16) char smem[G1_SMEM];
    const unsigned sb = smem_u32(smem);
    const int m0 = blockIdx.x * 32;
    const int tx = threadIdx.x, wid = tx >> 5, lane = tx & 31;
    const int wm = (wid >= 5) ? 1 : 0, wn = wid - wm * 5;
    const int i1 = SROWS * ip[0] + 1;
    const int lrow = (lane & 7) + ((lane & 8) ? 8 : 0);
    const int lcol = (lane & 16) ? 8 : 0;

    float acc[2][2][4];
#pragma unroll
    for (int c = 0; c < 2; ++c)
#pragma unroll
        for (int j = 0; j < 2; ++j)
#pragma unroll
            for (int q = 0; q < 4; ++q) acc[c][j][q] = 0.f;

    // A staging mapping (first 256 threads): 32 tok x 32 k per tile
    const int at = tx >> 3, au = (tx & 7) * 4;
    const int am = m0 + at;
    const float* axr = x + (size_t)am * DD + au;
    const float* apr = ((am % S) == 0)
        ? state + ((size_t)(am / S) * SROWS + i1) * DD + au
        : axr - DD;

#pragma unroll 1
    for (int kt = 0; kt < 64; ++kt) {
        const int k0 = kt * 32;
        if (tx < 256) {
            const float4 xv = *(const float4*)(axr + k0);
            const float4 pv = *(const float4*)(apr + k0);
            const float4 tv = *(const float4*)(tmx + k0 + au);
            const float x0 = fmaf(pv.x - xv.x, tv.x, xv.x);
            const float x1 = fmaf(pv.y - xv.y, tv.y, xv.y);
            const float x2 = fmaf(pv.z - xv.z, tv.z, xv.z);
            const float x3 = fmaf(pv.w - xv.w, tv.w, xv.w);
            const unsigned h0 = packbf2(x0, x1), h1 = packbf2(x2, x3);
            const float e0 = __uint_as_float(h0 << 16), e1 = __uint_as_float(h0 & 0xFFFF0000u);
            const float e2 = __uint_as_float(h1 << 16), e3 = __uint_as_float(h1 & 0xFFFF0000u);
            *(uint2*)(smem + (at * G1_ASTR + au) * 2)      = make_uint2(h0, h1);
            *(uint2*)(smem + (at * G1_ASTR + 32 + au) * 2) =
                make_uint2(packbf2(x0 - e0, x1 - e1), packbf2(x2 - e2, x3 - e3));
        }
#pragma unroll
        for (int p = 0; p < 2; ++p) {            // B: 640 uint4 per plane-pair
            const int idx = tx + p * 320;
            const int k = idx / 20, q = idx - k * 20;
            const size_t go = (size_t)(k0 + k) * NN1 + q * 8;
            const unsigned so = (unsigned)(k * G1_BSTR + q * 8) * 2;
            *(uint4*)(smem + G1_BHI + so) = *(const uint4*)(g_W1hi + go);
            *(uint4*)(smem + G1_BLO + so) = *(const uint4*)(g_W1lo + go);
        }
        __syncthreads();

        unsigned ahi[2][4], alo[2][4];
        {
            const unsigned abase = sb + G1_AS + ((wm * 16 + lrow) * G1_ASTR) * 2;
#pragma unroll
            for (int s = 0; s < 2; ++s) {
                LDSM_X4(ahi[s], abase + (s * 16 + lcol) * 2);
                LDSM_X4(alo[s], abase + (32 + s * 16 + lcol) * 2);
            }
        }
#pragma unroll
        for (int c = 0; c < 2; ++c) {
            const int ncol = wn * 32 + c * 16 + lcol;
            unsigned bh[2][4], bl[2][4];
#pragma unroll
            for (int s = 0; s < 2; ++s) {
                LDSM_X4T(bh[s], sb + G1_BHI + ((s * 16 + lrow) * G1_BSTR + ncol) * 2);
                LDSM_X4T(bl[s], sb + G1_BLO + ((s * 16 + lrow) * G1_BSTR + ncol) * 2);
            }
#pragma unroll
            for (int j = 0; j < 2; ++j)
#pragma unroll
                for (int s = 0; s < 2; ++s) {
                    MMA16816(acc[c][j], ahi[s], bh[s][2 * j], bh[s][2 * j + 1]);
                    MMA16816(acc[c][j], alo[s], bh[s][2 * j], bh[s][2 * j + 1]);
                    MMA16816(acc[c][j], ahi[s], bl[s][2 * j], bl[s][2 * j + 1]);
                }
        }
        __syncthreads();
    }

    // epilogue: tanh -> H bf16 hi/lo planes, straight from fragments
    const int crow = wm * 16 + (lane >> 2);
    const int ccol0 = wn * 32 + (lane & 3) * 2;
#pragma unroll
    for (int c = 0; c < 2; ++c)
#pragma unroll
        for (int j = 0; j < 2; ++j) {
            const int n = ccol0 + c * 16 + j * 8;
#pragma unroll
            for (int r = 0; r < 2; ++r) {
                const int m = m0 + crow + r * 8;
                const float t0 = ftanh(acc[c][j][r * 2]);
                const float t1 = ftanh(acc[c][j][r * 2 + 1]);
                const unsigned h = packbf2(t0, t1);
                const float e0 = __uint_as_float(h << 16);
                const float e1 = __uint_as_float(h & 0xFFFF0000u);
                *(unsigned*)&g_Hhi[(size_t)m * NN1 + n] = h;
                *(unsigned*)&g_Hlo[(size_t)m * NN1 + n] = packbf2(t0 - e0, t1 - e1);
            }
        }
}

// ============================================================================
// Kernel 2: mma.sync bf16x3 GEMM2 + fused combine, epilogue from fragments.
//   CTA: 64 tok x 256 d; warp = 16 tok x 64 d per half; 2 halves of 128 d.
// ============================================================================
#define AS_OFF   0
#define BHI_OFF  9216
#define BLO_OFF  26112
#define ASTRIDE  72
#define BSTRIDE  264
#define SMEM_SZ  43008

__global__ __launch_bounds__(256, 2) void k_gemm2(
    const float* __restrict__ x, const float* __restrict__ state,
    const float* __restrict__ mk, const float* __restrict__ mw,
    const float* __restrict__ mv, const float* __restrict__ mr,
    const float* __restrict__ mg,
    const int* __restrict__ ip, float* __restrict__ out, int S)
{
    extern __shared__ __align__(16) char smem[];
    const unsigned sb = smem_u32(smem);
    const int m0 = blockIdx.x * 64, dbase = blockIdx.y * 256;
    const int tx = threadIdx.x, wid = tx >> 5, lane = tx & 31;
    const int wm = wid & 3, wn = wid >> 2;
    const int i1 = SROWS * ip[0] + 1;
    const int lrow = (lane & 7) + ((lane & 8) ? 8 : 0);
    const int lcol = (lane & 16) ? 8 : 0;
    const int trow = wm * 16 + (lane >> 2);
    const int tcol = wn * 64 + (lane & 3) * 2;

#pragma unroll 1
    for (int f = 0; f < 5; ++f) {
        // ---- stage A: H planes [t][hi 0..31 | lo 32..63], pad 72 ----
#pragma unroll
        for (int i = 0; i < 4; ++i) {
            const int idx = tx + i * 256;            // 1024 uint2
            const int plane = idx >> 9, r = idx & 511, t = r >> 3, u = r & 7;
            const u16* src = (plane ? g_Hlo : g_Hhi) + (size_t)(m0 + t) * NN1 + f * 32 + u * 4;
            *(uint2*)(smem + AS_OFF + (t * ASTRIDE + plane * 32 + u * 4) * 2) = *(const uint2*)src;
        }
        // ---- stage B: w2 planes [k][d 0..255], pad 264 ----
#pragma unroll
        for (int i = 0; i < 8; ++i) {
            const int idx = tx + i * 256;            // 2048 uint4
            const int plane = idx >> 10, r = idx & 1023, k = r >> 5, u = r & 31;
            const u16* src = (plane ? g_Wlo : g_Whi) + (size_t)(f * 32 + k) * DD + dbase + u * 8;
            *(uint4*)(smem + (plane ? BLO_OFF : BHI_OFF) + (k * BSTRIDE + u * 8) * 2) = *(const uint4*)src;
        }
        __syncthreads();

        unsigned ahi[2][4], alo[2][4];
        {
            const unsigned abase = sb + AS_OFF + ((wm * 16 + lrow) * ASTRIDE) * 2;
#pragma unroll
            for (int s = 0; s < 2; ++s) {
                LDSM_X4(ahi[s], abase + (s * 16 + lcol) * 2);
                LDSM_X4(alo[s], abase + (32 + s * 16 + lcol) * 2);
            }
        }

        const float* maa = (f == 0 ? mk : f == 1 ? mw : f == 2 ? mv : f == 3 ? mr : mg);

#pragma unroll 1
        for (int h = 0; h < 2; ++h) {
            float acc[4][2][4];
#pragma unroll
            for (int c = 0; c < 4; ++c)
#pragma unroll
                for (int j = 0; j < 2; ++j)
#pragma unroll
                    for (int q = 0; q < 4; ++q) acc[c][j][q] = 0.f;

#pragma unroll 1
            for (int c = 0; c < 4; ++c) {
                const int ncol = h * 128 + wn * 64 + c * 16 + lcol;
                unsigned bh[2][4], bl[2][4];
#pragma unroll
                for (int s = 0; s < 2; ++s) {
                    LDSM_X4T(bh[s], sb + BHI_OFF + ((s * 16 + lrow) * BSTRIDE + ncol) * 2);
                    LDSM_X4T(bl[s], sb + BLO_OFF + ((s * 16 + lrow) * BSTRIDE + ncol) * 2);
                }
#pragma unroll
                for (int j = 0; j < 2; ++j)
#pragma unroll
                    for (int s = 0; s < 2; ++s) {
                        MMA16816(acc[c][j], ahi[s], bh[s][2 * j], bh[s][2 * j + 1]);
                        MMA16816(acc[c][j], alo[s], bh[s][2 * j], bh[s][2 * j + 1]);
                        MMA16816(acc[c][j], ahi[s], bl[s][2 * j], bl[s][2 * j + 1]);
                    }
            }

            // ---- epilogue straight from fragments (32B-sector float2) ----
            const int dch = dbase + h * 128;
#pragma unroll
            for (int r = 0; r < 2; ++r) {
                const int m = m0 + trow + r * 8;
                const float* xr = x + (size_t)m * DD + dch;
                const float* pr = ((m % S) == 0)
                    ? state + ((size_t)(m / S) * SROWS + i1) * DD + dch
                    : xr - DD;
                float* orow = out + ((size_t)m * 5 + f) * DD + dch;
#pragma unroll
                for (int c = 0; c < 4; ++c)
#pragma unroll
                    for (int j = 0; j < 2; ++j) {
                        const int off = tcol + c * 16 + j * 8;
                        const float2 xv = *(const float2*)(xr + off);
                        const float2 pv = *(const float2*)(pr + off);
                        const float2 mm = *(const float2*)(maa + dch + off);
                        const float a0 = acc[c][j][r * 2], a1 = acc[c][j][r * 2 + 1];
                        float2 o;
                        o.x = fmaf(pv.x - xv.x, mm.x + a0, xv.x);
                        o.y = fmaf(pv.y - xv.y, mm.y + a1, xv.y);
                        *(float2*)(orow + off) = o;
                    }
            }
        }
        __syncthreads();   // all ldmatrix reads done before next f restage
    }
}

// ============================================================================
// Kernel 3: new_state = state with row i1 replaced by x[:, S-1, :]
// ============================================================================
__global__ void k_state(const float* __restrict__ x, const float* __restrict__ state,
                        const int* __restrict__ ip, float* __restrict__ out2,
                        int S, int total4)
{
    const int idx = blockIdx.x * blockDim.x + threadIdx.x;
    if (idx >= total4) return;
    const int i1 = SROWS * ip[0] + 1;
    const int D4 = DD / 4;
    const int d4 = idx & (D4 - 1), r = (idx / D4) % SROWS, b = idx / (D4 * SROWS);
    float4 v;
    if (r == i1) v = ((const float4*)x)[((size_t)b * S + (S - 1)) * D4 + d4];
    else         v = ((const float4*)state)[idx];
    ((float4*)out2)[idx] = v;
}

extern "C" void kernel_launch(void* const* d_in, const int* in_sizes, int n_in,
                              void* d_out, int out_size)
{
    const float* x     = (const float*)d_in[0];
    const float* state = (const float*)d_in[1];
    const float* tmx   = (const float*)d_in[2];
    const float* w1    = (const float*)d_in[3];
    const float* w2    = (const float*)d_in[4];
    const float* mk    = (const float*)d_in[5];
    const float* mw    = (const float*)d_in[6];
    const float* mv    = (const float*)d_in[7];
    const float* mr    = (const float*)d_in[8];
    const float* mg    = (const float*)d_in[9];
    const int*   ip    = (const int*)  d_in[10];
    float* out = (float*)d_out;

    const int B = in_sizes[1] / (SROWS * DD);
    const int S = in_sizes[0] / (B * DD);
    const int M = B * S;

    const int w4 = (2048 * NN1) / 4;   // 81920, same element count for w1 and w2
    k_w1cvt<<<(w4 + 255) / 256, 256>>>(w1, w4);
    k_w2cvt<<<(w4 + 255) / 256, 256>>>(w2, w4);

    k_gemm1<<<M / 32, 320>>>(x, state, tmx, ip, S);
    k_gemm2<<<dim3(M / 64, DD / 256), 256, SMEM_SZ>>>(x, state, mk, mw, mv, mr, mg, ip, out, S);

    const long long kw = (long long)M * 5 * DD;
    const int st_total = B * SROWS * DD;
    if ((long long)out_size >= kw + (long long)st_total) {
        k_state<<<(st_total / 4 + 255) / 256, 256>>>(x, state, ip, out + kw, S, st_total / 4);
    }
}